// round 3
// baseline (speedup 1.0000x reference)
#include <cuda_runtime.h>
#include <cstdint>
#include <math.h>

#define N_NODES 25000
#define N_EDGES 400000
#define ROWS    50000
#define DIM     128
#define INV_DT  5.0f   // fp32(1.0f / fp32(0.2)) == 5.0f exactly; XLA:CPU fast-math
                       // rewrites ts/DELTAT into ts * 5.0f — we must match it.

// ---------------- device scratch (static; no allocation) ----------------
__device__ float g_Xq[(size_t)N_NODES * DIM];  // x@WQ_top + qt (bias folded)
__device__ float g_Xk[(size_t)N_NODES * DIM];
__device__ float g_Xv[(size_t)N_NODES * DIM];
__device__ float g_Tk[(size_t)ROWS * DIM];
__device__ float g_Tv[(size_t)ROWS * DIM];
__device__ float g_s[N_NODES];
__device__ float g_qt[DIM];
__device__ int   g_is64;

// ---------------- helpers ----------------
union U64F2 { unsigned long long u; float2 f; };

__device__ __forceinline__ unsigned long long fma2(unsigned long long a,
                                                   unsigned long long b,
                                                   unsigned long long c) {
    unsigned long long d;
    asm("fma.rn.f32x2 %0, %1, %2, %3;" : "=l"(d) : "l"(a), "l"(b), "l"(c));
    return d;
}

__device__ __forceinline__ int bucket(float tval) {
    // floor(t * 5.0f) with IEEE fp32 multiply, clipped to [0, ROWS-1]
    int idx = (int)floorf(__fmul_rn(tval, INV_DT));
    return max(0, min(idx, ROWS - 1));
}

// ---------------- edge_index dtype detection ----------------
// int64 little-endian values < 2^31 -> every odd int32 word is 0.
__global__ void detect_kernel(const int* __restrict__ ei) {
    int all0 = 1;
    for (int i = 0; i < 32; i++)
        if (ei[2 * i + 1] != 0) all0 = 0;
    g_is64 = all0;
}

// ---------------- qt = phi(t) @ WQ_bot (fp32) ----------------
__global__ void qt_kernel(const float* __restrict__ TE,
                          const float* __restrict__ WQ,
                          const float* __restrict__ t) {
    int idx = bucket(t[0]);
    const float* phi = TE + (size_t)idx * DIM;
    int o = threadIdx.x;
    float acc = 0.0f;
    #pragma unroll 8
    for (int k = 0; k < DIM; k++)
        acc += phi[k] * WQ[(size_t)(DIM + k) * DIM + o];
    g_qt[o] = acc;
}

__global__ void zero_s_kernel() {
    int i = blockIdx.x * 256 + threadIdx.x;
    if (i < N_NODES) g_s[i] = 0.0f;
}

// ---------------- C[M x 128] = A[M x 128] @ W[128 x 128] (+bias) ----------
// block = 128 threads; tile = 32 rows x 128 cols
// thread: cg = tid&31 -> cols 4cg..4cg+3 ; rg = tid>>5 -> rows 8rg..8rg+7
// packed f32x2 FMA for 2x fp32 rate.
__global__ void __launch_bounds__(128) gemm128(const float* __restrict__ A, int M,
                                               const float* __restrict__ W,
                                               float* __restrict__ C,
                                               const float* __restrict__ bias) {
    __shared__ float2 As[32][DIM];   // value duplicated into both packed lanes
    int tid = threadIdx.x;
    int rb = blockIdx.x * 32;

    for (int i = tid; i < 32 * DIM; i += 128) {
        int r = i >> 7, k = i & 127;
        int row = rb + r;
        float v = (row < M) ? A[(size_t)row * DIM + k] : 0.0f;
        As[r][k] = make_float2(v, v);
    }
    __syncthreads();

    int cg = tid & 31;
    int rg = tid >> 5;

    unsigned long long acc[8][2];
    #pragma unroll
    for (int r = 0; r < 8; r++) { acc[r][0] = 0ull; acc[r][1] = 0ull; }

    const ulonglong2* Wp = (const ulonglong2*)W;   // 16B = 4 floats = 2 pairs
    #pragma unroll 4
    for (int k = 0; k < DIM; k++) {
        ulonglong2 w = Wp[k * 32 + cg];            // W[k][4cg..4cg+3]
        #pragma unroll
        for (int r = 0; r < 8; r++) {
            unsigned long long x2 =
                *(const unsigned long long*)&As[rg * 8 + r][k];
            acc[r][0] = fma2(x2, w.x, acc[r][0]);
            acc[r][1] = fma2(x2, w.y, acc[r][1]);
        }
    }

    float b0 = 0.f, b1 = 0.f, b2 = 0.f, b3 = 0.f;
    if (bias) {
        float4 b = ((const float4*)bias)[cg];
        b0 = b.x; b1 = b.y; b2 = b.z; b3 = b.w;
    }
    #pragma unroll
    for (int r = 0; r < 8; r++) {
        int row = rb + rg * 8 + r;
        if (row < M) {
            U64F2 u0, u1; u0.u = acc[r][0]; u1.u = acc[r][1];
            float4 o = make_float4(u0.f.x + b0, u0.f.y + b1,
                                   u1.f.x + b2, u1.f.y + b3);
            ((float4*)C)[(size_t)row * 32 + cg] = o;
        }
    }
}

// ---------------- fused edge pass: one warp per edge ----------------
__global__ void __launch_bounds__(256) edge_kernel(const void* __restrict__ ei_raw,
                                                   const float* __restrict__ ts,
                                                   float* __restrict__ out) {
    int gw = (blockIdx.x * 256 + threadIdx.x) >> 5;
    int lane = threadIdx.x & 31;
    if (gw >= N_EDGES) return;

    int src, dst;
    if (g_is64) {
        const long long* p = (const long long*)ei_raw;
        src = (int)p[gw];
        dst = (int)p[N_EDGES + gw];
    } else {
        const int* p = (const int*)ei_raw;
        src = p[gw];
        dst = p[N_EDGES + gw];
    }
    int idx = bucket(__ldg(ts + gw));

    const float4* q4  = (const float4*)g_Xq + (size_t)dst * 32;
    const float4* k4  = (const float4*)g_Xk + (size_t)src * 32;
    const float4* tk4 = (const float4*)g_Tk + (size_t)idx * 32;

    float4 q  = q4[lane];
    float4 k  = k4[lane];
    float4 tk = tk4[lane];
    float part = q.x * (k.x + tk.x) + q.y * (k.y + tk.y) +
                 q.z * (k.z + tk.z) + q.w * (k.w + tk.w);
    #pragma unroll
    for (int off = 16; off; off >>= 1)
        part += __shfl_xor_sync(0xffffffffu, part, off);

    float w = expf(part);   // segment max skipped: |alpha| << 88, s >= 1

    const float4* v4  = (const float4*)g_Xv + (size_t)src * 32;
    const float4* tv4 = (const float4*)g_Tv + (size_t)idx * 32;
    float4 v  = v4[lane];
    float4 tv = tv4[lane];
    float4 r = make_float4(w * (v.x + tv.x), w * (v.y + tv.y),
                           w * (v.z + tv.z), w * (v.w + tv.w));

    // 16B vector reduction (sm_90+ native float4 atomicAdd -> RED)
    atomicAdd(((float4*)(out + (size_t)dst * DIM)) + lane, r);
    if (lane == 0)
        atomicAdd(g_s + dst, w);
}

__global__ void norm_kernel(float* __restrict__ out) {
    int i = blockIdx.x * 256 + threadIdx.x;
    if (i < N_NODES * DIM)
        out[i] = out[i] / (g_s[i >> 7] + 1e-16f);
}

// ---------------- launch ----------------
extern "C" void kernel_launch(void* const* d_in, const int* in_sizes, int n_in,
                              void* d_out, int out_size) {
    const float* x  = (const float*)d_in[0];
    const void*  ei = d_in[1];
    const float* ts = (const float*)d_in[2];
    const float* t  = (const float*)d_in[3];
    const float* TE = (const float*)d_in[4];
    const float* WQ = (const float*)d_in[5];
    const float* WK = (const float*)d_in[6];
    const float* WV = (const float*)d_in[7];
    float* out = (float*)d_out;

    float *Xq, *Xk, *Xv, *Tk, *Tv, *qt;
    cudaGetSymbolAddress((void**)&Xq, g_Xq);
    cudaGetSymbolAddress((void**)&Xk, g_Xk);
    cudaGetSymbolAddress((void**)&Xv, g_Xv);
    cudaGetSymbolAddress((void**)&Tk, g_Tk);
    cudaGetSymbolAddress((void**)&Tv, g_Tv);
    cudaGetSymbolAddress((void**)&qt, g_qt);

    detect_kernel<<<1, 1>>>((const int*)ei);
    qt_kernel<<<1, DIM>>>(TE, WQ, t);
    zero_s_kernel<<<(N_NODES + 255) / 256, 256>>>();
    cudaMemsetAsync(d_out, 0, (size_t)N_NODES * DIM * sizeof(float));

    int nb_node  = (N_NODES + 31) / 32;
    int nb_table = (ROWS + 31) / 32;
    gemm128<<<nb_node, 128>>>(x, N_NODES, WQ, Xq, qt);                 // Q top + qt
    gemm128<<<nb_node, 128>>>(x, N_NODES, WK, Xk, nullptr);            // K top
    gemm128<<<nb_node, 128>>>(x, N_NODES, WV, Xv, nullptr);            // V top
    gemm128<<<nb_table, 128>>>(TE, ROWS, WK + (size_t)DIM * DIM, Tk, nullptr); // K bot
    gemm128<<<nb_table, 128>>>(TE, ROWS, WV + (size_t)DIM * DIM, Tv, nullptr); // V bot

    edge_kernel<<<(N_EDGES * 32 + 255) / 256, 256>>>(ei, ts, out);
    norm_kernel<<<(N_NODES * DIM + 255) / 256, 256>>>(out);
}